// round 1
// baseline (speedup 1.0000x reference)
#include <cuda_runtime.h>
#include <cuda_bf16.h>
#include <mma.h>

using namespace nvcuda;

#define BATCH 32
#define TLEN  512
#define DDIM  1024
#define MROWS (BATCH * TLEN)   // 16384

#define BM 128
#define BN 128
#define BK 32

// ---------------- scratch (__device__ globals; no allocation allowed) ----------------
__device__ __nv_bfloat16 g_aq [(size_t)MROWS * DDIM];   // quantized activations (integers, exact in bf16)
__device__ float         g_inv_s[MROWS];                // per-row 1/s
__device__ __nv_bfloat16 g_xhi[(size_t)MROWS * DDIM];   // hi part of raw x
__device__ __nv_bfloat16 g_xlo[(size_t)MROWS * DDIM];   // lo part of raw x
__device__ __nv_bfloat16 g_wf [(size_t)DDIM * DDIM];    // sign(W_f)
__device__ __nv_bfloat16 g_wc [(size_t)DDIM * DDIM];    // sign(W_c)
__device__ __nv_bfloat16 g_wgs[(size_t)DDIM * DDIM];    // sign(W_g)
__device__ __nv_bfloat16 g_wgr[(size_t)DDIM * DDIM];    // raw W_g (for copy gate)
__device__ float g_F [(size_t)MROWS * DDIM];
__device__ float g_C [(size_t)MROWS * DDIM];
__device__ float g_G [(size_t)MROWS * DDIM];
__device__ float g_CG[(size_t)MROWS * DDIM];

__device__ __forceinline__ float sigmoidf_(float z) { return 1.0f / (1.0f + expf(-z)); }

// ---------------- weight conversion ----------------
__global__ void conv_w_kernel(const float* __restrict__ wf,
                              const float* __restrict__ wc,
                              const float* __restrict__ wg) {
    int i = blockIdx.x * 256 + threadIdx.x;
    if (i >= DDIM * DDIM) return;
    float a = wf[i], b = wc[i], c = wg[i];
    g_wf [i] = __float2bfloat16((a > 0.f) ? 1.f : ((a < 0.f) ? -1.f : 0.f));
    g_wc [i] = __float2bfloat16((b > 0.f) ? 1.f : ((b < 0.f) ? -1.f : 0.f));
    g_wgs[i] = __float2bfloat16((c > 0.f) ? 1.f : ((c < 0.f) ? -1.f : 0.f));
    g_wgr[i] = __float2bfloat16(c);  // ternary -> exact
}

// ---------------- rmsnorm + act_quant + hi/lo split (one block per row) ----------------
__global__ __launch_bounds__(256) void prep_kernel(const float* __restrict__ x,
                                                   const float* __restrict__ scale) {
    __shared__ float red[256];
    int m = blockIdx.x;
    int t = threadIdx.x;
    const float4* xr = (const float4*)(x + (size_t)m * DDIM);
    float4 xv = xr[t];
    float4 sv = ((const float4*)scale)[t];

    float ss = xv.x * xv.x + xv.y * xv.y + xv.z * xv.z + xv.w * xv.w;
    red[t] = ss; __syncthreads();
    for (int s = 128; s > 0; s >>= 1) { if (t < s) red[t] += red[t + s]; __syncthreads(); }
    float rstd = rsqrtf(red[0] * (1.0f / DDIM) + 1e-5f);
    __syncthreads();

    float y0 = sv.x * xv.x * rstd, y1 = sv.y * xv.y * rstd;
    float y2 = sv.z * xv.z * rstd, y3 = sv.w * xv.w * rstd;
    float am = fmaxf(fmaxf(fabsf(y0), fabsf(y1)), fmaxf(fabsf(y2), fabsf(y3)));
    red[t] = am; __syncthreads();
    for (int s = 128; s > 0; s >>= 1) { if (t < s) red[t] = fmaxf(red[t], red[t + s]); __syncthreads(); }
    float amax = red[0];

    float s_q = fminf(fmaxf(127.0f / (amax + 1e-5f), 0.001f), 1000.0f);
    if (t == 0) g_inv_s[m] = 1.0f / s_q;

    float q0 = fminf(fmaxf(rintf(s_q * y0), -128.f), 127.f);
    float q1 = fminf(fmaxf(rintf(s_q * y1), -128.f), 127.f);
    float q2 = fminf(fmaxf(rintf(s_q * y2), -128.f), 127.f);
    float q3 = fminf(fmaxf(rintf(s_q * y3), -128.f), 127.f);

    union { __nv_bfloat16 h[4]; uint2 u; } pq, ph, pl;
    pq.h[0] = __float2bfloat16(q0); pq.h[1] = __float2bfloat16(q1);
    pq.h[2] = __float2bfloat16(q2); pq.h[3] = __float2bfloat16(q3);
    float xa[4] = {xv.x, xv.y, xv.z, xv.w};
#pragma unroll
    for (int i = 0; i < 4; i++) {
        ph.h[i] = __float2bfloat16(xa[i]);
        pl.h[i] = __float2bfloat16(xa[i] - __bfloat162float(ph.h[i]));
    }
    size_t off = (size_t)m * DDIM + t * 4;
    *(uint2*)&g_aq [off] = pq.u;
    *(uint2*)&g_xhi[off] = ph.u;
    *(uint2*)&g_xlo[off] = pl.u;
}

// ---------------- quantized-path GEMM + fused activation epilogue ----------------
// MODE 0: F = sigmoid(aq@sign(Wf)*inv_s + bf)
// MODE 1: C = silu   (aq@sign(Wc)*inv_s + bc)
// MODE 2: G = sigmoid(aq@sign(Wg)*inv_s + bg)
template <int MODE>
__global__ __launch_bounds__(256) void gemm_q_kernel(const float* __restrict__ bias) {
    const __nv_bfloat16* __restrict__ W = (MODE == 0) ? g_wf : (MODE == 1) ? g_wc : g_wgs;
    float* __restrict__ out = (MODE == 0) ? g_F : (MODE == 1) ? g_C : g_G;

    __shared__ __nv_bfloat16 As[BM][BK + 8];   // ld 40 elems = 80B (16B multiple)
    __shared__ __nv_bfloat16 Bs[BK][BN + 8];   // ld 136 elems = 272B
    __shared__ float epi[8][16][16];

    int tid = threadIdx.x;
    int warpId = tid >> 5;
    int wm = warpId & 3, wn = warpId >> 2;     // 4x2 warp grid, warp tile 32x64
    int bm = blockIdx.x * BM, bn = blockIdx.y * BN;

    wmma::fragment<wmma::accumulator, 16, 16, 16, float> acc[2][4];
#pragma unroll
    for (int i = 0; i < 2; i++)
#pragma unroll
        for (int j = 0; j < 4; j++) wmma::fill_fragment(acc[i][j], 0.0f);

    for (int k0 = 0; k0 < DDIM; k0 += BK) {
#pragma unroll
        for (int i = 0; i < 2; i++) {
            int ci = tid + i * 256;
            int r  = ci >> 2,  c8  = (ci & 3)  * 8;
            *(uint4*)&As[r][c8]   = *(const uint4*)&g_aq[(size_t)(bm + r) * DDIM + k0 + c8];
            int rb = ci >> 4,  cb8 = (ci & 15) * 8;
            *(uint4*)&Bs[rb][cb8] = *(const uint4*)&W[(size_t)(k0 + rb) * DDIM + bn + cb8];
        }
        __syncthreads();
#pragma unroll
        for (int ks = 0; ks < BK; ks += 16) {
            wmma::fragment<wmma::matrix_a, 16, 16, 16, __nv_bfloat16, wmma::row_major> af[2];
            wmma::fragment<wmma::matrix_b, 16, 16, 16, __nv_bfloat16, wmma::row_major> bfr[4];
#pragma unroll
            for (int i = 0; i < 2; i++)
                wmma::load_matrix_sync(af[i], &As[wm * 32 + i * 16][ks], BK + 8);
#pragma unroll
            for (int j = 0; j < 4; j++)
                wmma::load_matrix_sync(bfr[j], &Bs[ks][wn * 64 + j * 16], BN + 8);
#pragma unroll
            for (int i = 0; i < 2; i++)
#pragma unroll
                for (int j = 0; j < 4; j++)
                    wmma::mma_sync(acc[i][j], af[i], bfr[j], acc[i][j]);
        }
        __syncthreads();
    }

    int lane = tid & 31;
#pragma unroll
    for (int i = 0; i < 2; i++)
#pragma unroll
        for (int j = 0; j < 4; j++) {
            wmma::store_matrix_sync(&epi[warpId][0][0], acc[i][j], 16, wmma::mem_row_major);
            __syncwarp();
#pragma unroll
            for (int e = 0; e < 8; e++) {
                int idx = lane + e * 32;
                int r = idx >> 4, c = idx & 15;
                int gm = bm + wm * 32 + i * 16 + r;
                int gn = bn + wn * 64 + j * 16 + c;
                float z = epi[warpId][r][c] * g_inv_s[gm] + bias[gn];
                float res = (MODE == 1) ? z * sigmoidf_(z) : sigmoidf_(z);
                out[(size_t)gm * DDIM + gn] = res;
            }
            __syncwarp();
        }
}

// ---------------- copy-gate GEMM: CG = sigmoid(x @ Wg^T), x = x_hi + x_lo ----------------
__global__ __launch_bounds__(256) void gemm_cg_kernel() {
    __shared__ __nv_bfloat16 Ah[BM][BK + 8];
    __shared__ __nv_bfloat16 Al[BM][BK + 8];
    __shared__ __nv_bfloat16 Bs[BN][BK + 8];   // Bs[n][k] -> col_major matrix_b
    __shared__ float epi[8][16][16];

    int tid = threadIdx.x;
    int warpId = tid >> 5;
    int wm = warpId & 3, wn = warpId >> 2;
    int bm = blockIdx.x * BM, bn = blockIdx.y * BN;

    wmma::fragment<wmma::accumulator, 16, 16, 16, float> acc[2][4];
#pragma unroll
    for (int i = 0; i < 2; i++)
#pragma unroll
        for (int j = 0; j < 4; j++) wmma::fill_fragment(acc[i][j], 0.0f);

    for (int k0 = 0; k0 < DDIM; k0 += BK) {
#pragma unroll
        for (int i = 0; i < 2; i++) {
            int ci = tid + i * 256;
            int r = ci >> 2, c8 = (ci & 3) * 8;
            size_t goff = (size_t)(bm + r) * DDIM + k0 + c8;
            *(uint4*)&Ah[r][c8] = *(const uint4*)&g_xhi[goff];
            *(uint4*)&Al[r][c8] = *(const uint4*)&g_xlo[goff];
            // B: row n of Wg (raw), 32 consecutive k
            *(uint4*)&Bs[r][c8] = *(const uint4*)&g_wgr[(size_t)(bn + r) * DDIM + k0 + c8];
        }
        __syncthreads();
#pragma unroll
        for (int ks = 0; ks < BK; ks += 16) {
            wmma::fragment<wmma::matrix_a, 16, 16, 16, __nv_bfloat16, wmma::row_major> ah[2], al[2];
            wmma::fragment<wmma::matrix_b, 16, 16, 16, __nv_bfloat16, wmma::col_major> bfr[4];
#pragma unroll
            for (int i = 0; i < 2; i++) {
                wmma::load_matrix_sync(ah[i], &Ah[wm * 32 + i * 16][ks], BK + 8);
                wmma::load_matrix_sync(al[i], &Al[wm * 32 + i * 16][ks], BK + 8);
            }
#pragma unroll
            for (int j = 0; j < 4; j++)
                wmma::load_matrix_sync(bfr[j], &Bs[wn * 64 + j * 16][ks], BK + 8);
#pragma unroll
            for (int i = 0; i < 2; i++)
#pragma unroll
                for (int j = 0; j < 4; j++) {
                    wmma::mma_sync(acc[i][j], ah[i], bfr[j], acc[i][j]);
                    wmma::mma_sync(acc[i][j], al[i], bfr[j], acc[i][j]);
                }
        }
        __syncthreads();
    }

    int lane = tid & 31;
#pragma unroll
    for (int i = 0; i < 2; i++)
#pragma unroll
        for (int j = 0; j < 4; j++) {
            wmma::store_matrix_sync(&epi[warpId][0][0], acc[i][j], 16, wmma::mem_row_major);
            __syncwarp();
#pragma unroll
            for (int e = 0; e < 8; e++) {
                int idx = lane + e * 32;
                int r = idx >> 4, c = idx & 15;
                int gm = bm + wm * 32 + i * 16 + r;
                int gn = bn + wn * 64 + j * 16 + c;
                g_CG[(size_t)gm * DDIM + gn] = sigmoidf_(epi[warpId][r][c]);
            }
            __syncwarp();
        }
}

// ---------------- elementwise recurrence: one thread per (b, d) lane ----------------
__global__ __launch_bounds__(128) void scan_kernel(const float* __restrict__ x,
                                                   const int* __restrict__ seqlen,
                                                   float* __restrict__ out) {
    int gid = blockIdx.x * blockDim.x + threadIdx.x;  // 0 .. 32767
    int b = gid >> 10;
    int d = gid & (DDIM - 1);
    int len = seqlen[b];
    size_t base = ((size_t)b * TLEN) * DDIM + d;
    float h = 0.0f;
#pragma unroll 8
    for (int t = 0; t < TLEN; t++) {
        size_t off = base + (size_t)t * DDIM;
        float f  = g_F[off];
        float c  = g_C[off];
        float g  = g_G[off];
        float cg = g_CG[off];
        float xv = x[off];
        float hn = f * h + (1.0f - f) * c;
        float o  = g * hn;
        h = cg * xv + (1.0f - cg) * hn;
        out[off] = (t < len) ? o : 0.0f;
    }
}

// ---------------- launcher ----------------
extern "C" void kernel_launch(void* const* d_in, const int* in_sizes, int n_in,
                              void* d_out, int out_size) {
    const float* x      = (const float*)d_in[0];
    const int*   seqlen = (const int*)  d_in[1];
    const float* scale  = (const float*)d_in[2];
    const float* Wf     = (const float*)d_in[3];
    const float* Wc     = (const float*)d_in[4];
    const float* Wg     = (const float*)d_in[5];
    const float* bf     = (const float*)d_in[6];
    const float* bc     = (const float*)d_in[7];
    const float* bg     = (const float*)d_in[8];
    float* out = (float*)d_out;

    conv_w_kernel<<<(DDIM * DDIM + 255) / 256, 256>>>(Wf, Wc, Wg);
    prep_kernel<<<MROWS, 256>>>(x, scale);

    dim3 grid(MROWS / BM, DDIM / BN);  // 128 x 8
    gemm_q_kernel<0><<<grid, 256>>>(bf);
    gemm_q_kernel<1><<<grid, 256>>>(bc);
    gemm_q_kernel<2><<<grid, 256>>>(bg);
    gemm_cg_kernel<<<grid, 256>>>();

    scan_kernel<<<(BATCH * DDIM) / 128, 128>>>(x, seqlen, out);
}